// round 9
// baseline (speedup 1.0000x reference)
#include <cuda_runtime.h>
#include <cuda_bf16.h>
#include <math.h>

// ---------------------------------------------------------------------------
// GAT layer (round 9): R8 + pass-major mma scheduling (ILP fix).
// ncu R8: k_gemm_qkv tensor=39.5%, issue=17%, latency-bound on dependent
// 3-pass mma chains -> reorder to hh-sweep / hl-sweep / lh-sweep.
// ---------------------------------------------------------------------------

#define NNODES 50000
#define NEDGES 640000
#define FDIM   128
#define DFF    512
#define SCAN_NB ((NNODES + 255) / 256)   // 196
#define RSTR   12                        // SMEM row stride in u32 words (48B)

// fp32 scratch
__device__ __align__(16) float g_q[NNODES * FDIM];
__device__ __align__(16) float g_k[NNODES * FDIM];
__device__ __align__(16) float g_v[NNODES * FDIM];
__device__ __align__(16) float g_rst[NNODES * FDIM];
__device__ __align__(16) float g_x[NNODES * FDIM];
// bf16 hi/lo activations
__device__ __align__(16) __nv_bfloat16 g_feat_h[NNODES * FDIM];
__device__ __align__(16) __nv_bfloat16 g_feat_l[NNODES * FDIM];
__device__ __align__(16) __nv_bfloat16 g_rst_h[NNODES * FDIM];
__device__ __align__(16) __nv_bfloat16 g_rst_l[NNODES * FDIM];
__device__ __align__(16) __nv_bfloat16 g_hbuf_h[NNODES * DFF];
__device__ __align__(16) __nv_bfloat16 g_hbuf_l[NNODES * DFF];
// transposed split weights: Wt[n][k] bf16 hi/lo
__device__ __align__(16) __nv_bfloat16 g_Wqt_h[FDIM * FDIM];
__device__ __align__(16) __nv_bfloat16 g_Wqt_l[FDIM * FDIM];
__device__ __align__(16) __nv_bfloat16 g_Wkt_h[FDIM * FDIM];
__device__ __align__(16) __nv_bfloat16 g_Wkt_l[FDIM * FDIM];
__device__ __align__(16) __nv_bfloat16 g_Wvt_h[FDIM * FDIM];
__device__ __align__(16) __nv_bfloat16 g_Wvt_l[FDIM * FDIM];
__device__ __align__(16) __nv_bfloat16 g_W1t_h[DFF * FDIM];
__device__ __align__(16) __nv_bfloat16 g_W1t_l[DFF * FDIM];
__device__ __align__(16) __nv_bfloat16 g_W2t_h[FDIM * DFF];
__device__ __align__(16) __nv_bfloat16 g_W2t_l[FDIM * DFF];
// CSR
__device__ int g_deg[NNODES];
__device__ int g_off[NNODES + 1];
__device__ int g_eid[NEDGES];
__device__ int g_bsum[256];

// ---------------------------------------------------------------- helpers
__device__ __forceinline__ void split2(float a, float b, unsigned& h,
                                       unsigned& l) {
    __nv_bfloat16 ha = __float2bfloat16_rn(a);
    __nv_bfloat16 hb = __float2bfloat16_rn(b);
    __nv_bfloat16 la = __float2bfloat16_rn(a - __bfloat162float(ha));
    __nv_bfloat16 lb = __float2bfloat16_rn(b - __bfloat162float(hb));
    __nv_bfloat162 hh, ll;
    hh.x = ha; hh.y = hb;
    ll.x = la; ll.y = lb;
    h = *(unsigned*)&hh;
    l = *(unsigned*)&ll;
}

#define MMA_BF16(C, A0, A1, A2, A3, B0, B1)                                   \
    asm volatile(                                                             \
        "mma.sync.aligned.m16n8k16.row.col.f32.bf16.bf16.f32 "                \
        "{%0,%1,%2,%3}, {%4,%5,%6,%7}, {%8,%9}, {%0,%1,%2,%3};"               \
        : "+f"((C)[0]), "+f"((C)[1]), "+f"((C)[2]), "+f"((C)[3])              \
        : "r"(A0), "r"(A1), "r"(A2), "r"(A3), "r"(B0), "r"(B1));

#define CPASYNC16(dst, src, sz)                                               \
    asm volatile("cp.async.cg.shared.global [%0], [%1], 16, %2;" ::           \
                     "r"(dst), "l"(src), "r"(sz))
#define CP_COMMIT() asm volatile("cp.async.commit_group;")
#define CP_WAIT1() asm volatile("cp.async.wait_group 1;")
#define CP_WAIT0() asm volatile("cp.async.wait_group 0;")

// one fused kernel: transpose+split all 5 weight matrices to bf16 hi/lo.
__global__ void k_split_wall(const float* __restrict__ Wq,
                             const float* __restrict__ Wk,
                             const float* __restrict__ Wv,
                             const float* __restrict__ W1,
                             const float* __restrict__ W2) {
    int i = blockIdx.x * blockDim.x + threadIdx.x;
    const float* in;
    __nv_bfloat16 *oh, *ol;
    int idx, K, N;
    if (i < 16384) {
        in = Wq; oh = g_Wqt_h; ol = g_Wqt_l; idx = i; K = FDIM; N = FDIM;
    } else if (i < 32768) {
        in = Wk; oh = g_Wkt_h; ol = g_Wkt_l; idx = i - 16384; K = FDIM; N = FDIM;
    } else if (i < 49152) {
        in = Wv; oh = g_Wvt_h; ol = g_Wvt_l; idx = i - 32768; K = FDIM; N = FDIM;
    } else if (i < 114688) {
        in = W1; oh = g_W1t_h; ol = g_W1t_l; idx = i - 49152; K = FDIM; N = DFF;
    } else if (i < 180224) {
        in = W2; oh = g_W2t_h; ol = g_W2t_l; idx = i - 114688; K = DFF; N = FDIM;
    } else {
        return;
    }
    int n = idx / K, k = idx - n * K;
    float x = in[(size_t)k * N + n];
    __nv_bfloat16 h = __float2bfloat16_rn(x);
    oh[idx] = h;
    ol[idx] = __float2bfloat16_rn(x - __bfloat162float(h));
}

// split feat (fp32, row-major) -> g_feat_h / g_feat_l
__global__ void k_split_feat(const float* __restrict__ in) {
    int i = blockIdx.x * blockDim.x + threadIdx.x;   // pair index
    if (i >= NNODES * FDIM / 2) return;
    float2 v = ((const float2*)in)[i];
    unsigned h, l;
    split2(v.x, v.y, h, l);
    ((unsigned*)g_feat_h)[i] = h;
    ((unsigned*)g_feat_l)[i] = l;
}

// ---------------------------------------------------------------- CSR build
__global__ void k_zero_deg() {
    int i = blockIdx.x * blockDim.x + threadIdx.x;
    if (i < NNODES) g_deg[i] = 0;
}
__global__ void k_hist(const int* __restrict__ dst) {
    int e = blockIdx.x * blockDim.x + threadIdx.x;
    if (e < NEDGES) atomicAdd(&g_deg[dst[e]], 1);
}
__global__ void k_scan1() {
    __shared__ int s[256];
    int b = blockIdx.x, t = threadIdx.x;
    int i = b * 256 + t;
    int v = (i < NNODES) ? g_deg[i] : 0;
    s[t] = v;
    __syncthreads();
#pragma unroll
    for (int off = 1; off < 256; off <<= 1) {
        int add = (t >= off) ? s[t - off] : 0;
        __syncthreads();
        s[t] += add;
        __syncthreads();
    }
    if (i < NNODES) g_off[i + 1] = s[t];
    if (t == 255) g_bsum[b] = s[t];
}
__global__ void k_scan2() {
    __shared__ int s[256];
    int t = threadIdx.x;
    int v = (t < SCAN_NB) ? g_bsum[t] : 0;
    s[t] = v;
    __syncthreads();
#pragma unroll
    for (int off = 1; off < 256; off <<= 1) {
        int add = (t >= off) ? s[t - off] : 0;
        __syncthreads();
        s[t] += add;
        __syncthreads();
    }
    if (t < SCAN_NB) g_bsum[t] = s[t] - v;
}
// scan3 also re-zeros g_deg for the scatter pass
__global__ void k_scan3() {
    int b = blockIdx.x, t = threadIdx.x;
    int i = b * 256 + t;
    if (i < NNODES) {
        g_off[i + 1] += g_bsum[b];
        g_deg[i] = 0;
    }
    if (i == 0) g_off[0] = 0;
}
__global__ void k_scatter(const int* __restrict__ dst) {
    int e = blockIdx.x * blockDim.x + threadIdx.x;
    if (e < NEDGES) {
        int d = dst[e];
        int pos = g_off[d] + atomicAdd(&g_deg[d], 1);
        g_eid[pos] = e;
    }
}

// ------------------------------------------------- MMA GEMM core (pipelined)
// BM=128, BN=128, BK=16, 256 threads = 8 warps (2 M x 4 N), warp tile 64x32.
// Pass-major mma sweeps: 16 independent accumulator chains per pass.
#define GEMM_MMA_BF(AHI, ALO, BTHI, BTLO, KTOT, COL0)                          \
    float acc[4][4][4];                                                       \
    _Pragma("unroll") for (int a_ = 0; a_ < 4; a_++)                          \
        _Pragma("unroll") for (int b_ = 0; b_ < 4; b_++)                      \
            _Pragma("unroll") for (int c_ = 0; c_ < 4; c_++)                  \
                acc[a_][b_][c_] = 0.f;                                        \
    __shared__ unsigned sm[2][4][128 * RSTR];                                 \
    const int tid = threadIdx.x;                                              \
    const int lane = tid & 31, wid = tid >> 5;                                \
    const int wm = wid >> 2, wn = wid & 3;                                    \
    const int g = lane >> 2, tk = lane & 3;                                   \
    const int row0 = blockIdx.y * 128;                                        \
    const int lr = tid >> 1, lh = tid & 1;                                    \
    int arow = row0 + lr;                                                     \
    const unsigned okA = (arow < NNODES) ? 16u : 0u;                          \
    if (arow >= NNODES) arow = NNODES - 1;                                    \
    const int brow = (COL0) + lr;                                             \
    const __nv_bfloat16* gsrc[4] = {                                          \
        (AHI) + (size_t)arow * (KTOT) + lh * 8,                               \
        (ALO) + (size_t)arow * (KTOT) + lh * 8,                               \
        (BTHI) + (size_t)brow * (KTOT) + lh * 8,                              \
        (BTLO) + (size_t)brow * (KTOT) + lh * 8};                             \
    const unsigned szs[4] = {okA, okA, 16u, 16u};                             \
    const unsigned smbase =                                                   \
        (unsigned)__cvta_generic_to_shared(&sm[0][0][0]) +                    \
        (unsigned)((lr * RSTR + lh * 4) * 4);                                 \
    const int NT = (KTOT) / 16;                                               \
    _Pragma("unroll") for (int a_ = 0; a_ < 4; a_++)                          \
        CPASYNC16(smbase + a_ * (128 * RSTR * 4), gsrc[a_], szs[a_]);         \
    CP_COMMIT();                                                              \
    for (int kt = 0; kt < NT; kt++) {                                         \
        if (kt + 1 < NT) {                                                    \
            unsigned sb = smbase + ((kt + 1) & 1) * (4 * 128 * RSTR * 4);     \
            _Pragma("unroll") for (int a_ = 0; a_ < 4; a_++)                  \
                CPASYNC16(sb + a_ * (128 * RSTR * 4),                         \
                          gsrc[a_] + (kt + 1) * 16, szs[a_]);                 \
            CP_COMMIT();                                                      \
            CP_WAIT1();                                                       \
        } else {                                                              \
            CP_WAIT0();                                                       \
        }                                                                     \
        __syncthreads();                                                      \
        const unsigned* As_h = sm[kt & 1][0];                                 \
        const unsigned* As_l = sm[kt & 1][1];                                 \
        const unsigned* Bs_h = sm[kt & 1][2];                                 \
        const unsigned* Bs_l = sm[kt & 1][3];                                 \
        unsigned ah[4][4], al[4][4], bh[4][2], bl[4][2];                      \
        _Pragma("unroll") for (int mt = 0; mt < 4; mt++) {                    \
            int br = wm * 64 + mt * 16;                                       \
            ah[mt][0] = As_h[(br + g) * RSTR + tk];                           \
            ah[mt][1] = As_h[(br + g + 8) * RSTR + tk];                       \
            ah[mt][2] = As_h[(br + g) * RSTR + tk + 4];                       \
            ah[mt][3] = As_h[(br + g + 8) * RSTR + tk + 4];                   \
            al[mt][0] = As_l[(br + g) * RSTR + tk];                           \
            al[mt][1] = As_l[(br + g + 8) * RSTR + tk];                       \
            al[mt][2] = As_l[(br + g) * RSTR + tk + 4];                       \
            al[mt][3] = As_l[(br + g + 8) * RSTR + tk + 4];                   \
        }                                                                     \
        _Pragma("unroll") for (int nt = 0; nt < 4; nt++) {                    \
            int bn = wn * 32 + nt * 8;                                        \
            bh[nt][0] = Bs_h[(bn + g) * RSTR + tk];                           \
            bh[nt][1] = Bs_h[(bn + g) * RSTR + tk + 4];                       \
            bl[nt][0] = Bs_l[(bn + g) * RSTR + tk];                           \
            bl[nt][1] = Bs_l[(bn + g) * RSTR + tk + 4];                       \
        }                                                                     \
        /* pass-major sweeps: 16 independent acc chains per pass */           \
        _Pragma("unroll") for (int mt = 0; mt < 4; mt++)                      \
            _Pragma("unroll") for (int nt = 0; nt < 4; nt++)                  \
                MMA_BF16(acc[mt][nt], ah[mt][0], ah[mt][1], ah[mt][2],        \
                         ah[mt][3], bh[nt][0], bh[nt][1]);                    \
        _Pragma("unroll") for (int mt = 0; mt < 4; mt++)                      \
            _Pragma("unroll") for (int nt = 0; nt < 4; nt++)                  \
                MMA_BF16(acc[mt][nt], ah[mt][0], ah[mt][1], ah[mt][2],        \
                         ah[mt][3], bl[nt][0], bl[nt][1]);                    \
        _Pragma("unroll") for (int mt = 0; mt < 4; mt++)                      \
            _Pragma("unroll") for (int nt = 0; nt < 4; nt++)                  \
                MMA_BF16(acc[mt][nt], al[mt][0], al[mt][1], al[mt][2],        \
                         al[mt][3], bh[nt][0], bh[nt][1]);                    \
        __syncthreads();                                                      \
    }

// QKV: grid (3, 391); blockIdx.x selects {q,k,v}
__global__ __launch_bounds__(256, 1) void k_gemm_qkv() {
    const int m = blockIdx.x;
    const __nv_bfloat16* Bh = (m == 0) ? g_Wqt_h : (m == 1) ? g_Wkt_h : g_Wvt_h;
    const __nv_bfloat16* Bl = (m == 0) ? g_Wqt_l : (m == 1) ? g_Wkt_l : g_Wvt_l;
    float* C = (m == 0) ? g_q : (m == 1) ? g_k : g_v;
    GEMM_MMA_BF(g_feat_h, g_feat_l, Bh, Bl, FDIM, 0)
#pragma unroll
    for (int mt = 0; mt < 4; mt++) {
#pragma unroll
        for (int nt = 0; nt < 4; nt++) {
            int row = row0 + wm * 64 + mt * 16 + g;
            int col = wn * 32 + nt * 8 + tk * 2;
#pragma unroll
            for (int hf = 0; hf < 2; hf++) {
                int r = row + hf * 8;
                if (r >= NNODES) continue;
                *(float2*)(C + (size_t)r * FDIM + col) =
                    make_float2(acc[mt][nt][hf * 2 + 0],
                                acc[mt][nt][hf * 2 + 1]);
            }
        }
    }
}

// FFN1: hbuf(hi/lo bf16) = PReLU(rst @ W1 + b1) ; grid (4, 391)
__global__ __launch_bounds__(256, 1) void k_ffn1(const float* __restrict__ b1,
                                                 const float* __restrict__ pa) {
    const int col0 = blockIdx.x * 128;
    GEMM_MMA_BF(g_rst_h, g_rst_l, g_W1t_h, g_W1t_l, FDIM, col0)
#pragma unroll
    for (int mt = 0; mt < 4; mt++) {
#pragma unroll
        for (int nt = 0; nt < 4; nt++) {
            int row = row0 + wm * 64 + mt * 16 + g;
            int col = col0 + wn * 32 + nt * 8 + tk * 2;
            float bb0 = b1[col], bb1 = b1[col + 1];
            float pa0 = pa[col], pa1 = pa[col + 1];
#pragma unroll
            for (int hf = 0; hf < 2; hf++) {
                int r = row + hf * 8;
                if (r >= NNODES) continue;
                float h0 = acc[mt][nt][hf * 2 + 0] + bb0;
                float h1 = acc[mt][nt][hf * 2 + 1] + bb1;
                h0 = (h0 >= 0.f) ? h0 : pa0 * h0;
                h1 = (h1 >= 0.f) ? h1 : pa1 * h1;
                unsigned hw, lw;
                split2(h0, h1, hw, lw);
                size_t w = ((size_t)r * DFF + col) >> 1;
                ((unsigned*)g_hbuf_h)[w] = hw;
                ((unsigned*)g_hbuf_l)[w] = lw;
            }
        }
    }
}

// FFN2: g_x = hbuf @ W2 + b2 + rst ; grid (1, 391)
__global__ __launch_bounds__(256, 1) void k_ffn2(const float* __restrict__ b2) {
    GEMM_MMA_BF(g_hbuf_h, g_hbuf_l, g_W2t_h, g_W2t_l, DFF, 0)
#pragma unroll
    for (int mt = 0; mt < 4; mt++) {
#pragma unroll
        for (int nt = 0; nt < 4; nt++) {
            int row = row0 + wm * 64 + mt * 16 + g;
            int col = wn * 32 + nt * 8 + tk * 2;
            float bb0 = b2[col], bb1 = b2[col + 1];
#pragma unroll
            for (int hf = 0; hf < 2; hf++) {
                int r = row + hf * 8;
                if (r >= NNODES) continue;
                float2 rv = *(const float2*)(g_rst + (size_t)r * FDIM + col);
                *(float2*)(g_x + (size_t)r * FDIM + col) =
                    make_float2(acc[mt][nt][hf * 2 + 0] + bb0 + rv.x,
                                acc[mt][nt][hf * 2 + 1] + bb1 + rv.y);
            }
        }
    }
}

// final LN over g_x -> out ; one warp per row
__global__ __launch_bounds__(256) void k_ln(const float* __restrict__ lng,
                                            const float* __restrict__ lnb,
                                            float* __restrict__ out) {
    int n = blockIdx.x * 8 + (threadIdx.x >> 5);
    int lane = threadIdx.x & 31;
    if (n >= NNODES) return;
    float4 x = *(const float4*)(g_x + (size_t)n * FDIM + lane * 4);
    float p = x.x + x.y + x.z + x.w;
#pragma unroll
    for (int o = 16; o; o >>= 1) p += __shfl_xor_sync(0xffffffffu, p, o);
    float mu = p * (1.f / 128.f);
    float d0 = x.x - mu, d1 = x.y - mu, d2 = x.z - mu, d3 = x.w - mu;
    float q = d0 * d0 + d1 * d1 + d2 * d2 + d3 * d3;
#pragma unroll
    for (int o = 16; o; o >>= 1) q += __shfl_xor_sync(0xffffffffu, q, o);
    float rs = rsqrtf(q * (1.f / 128.f) + 1e-5f);
    const float4 gv = *(const float4*)(lng + lane * 4);
    const float4 lb = *(const float4*)(lnb + lane * 4);
    *(float4*)(out + (size_t)n * FDIM + lane * 4) =
        make_float4(d0 * rs * gv.x + lb.x, d1 * rs * gv.y + lb.y,
                    d2 * rs * gv.z + lb.z, d3 * rs * gv.w + lb.w);
}

// --------------------------------------------- attention aggregate + LN1
__global__ __launch_bounds__(256) void k_aggregate(
    const float* __restrict__ feat, const int* __restrict__ src,
    const float* __restrict__ lng, const float* __restrict__ lnb) {
    int n = (blockIdx.x * blockDim.x + threadIdx.x) >> 5;
    int lane = threadIdx.x & 31;
    if (n >= NNODES) return;

    const float4 q4 = *(const float4*)(g_q + (size_t)n * FDIM + lane * 4);
    float4 acc = make_float4(0.f, 0.f, 0.f, 0.f);
    float m = -INFINITY, s = 0.f;
    const float rscale = 0.08838834764831845f;   // 1/sqrt(128)

    int beg = g_off[n], end = g_off[n + 1];
    for (int idx = beg; idx < end; ++idx) {
        int e = g_eid[idx];
        int sn = src[e];
        const float4 k4 = *(const float4*)(g_k + (size_t)sn * FDIM + lane * 4);
        const float4 v4 = *(const float4*)(g_v + (size_t)sn * FDIM + lane * 4);
        float p = k4.x * q4.x + k4.y * q4.y + k4.z * q4.z + k4.w * q4.w;
        p += __shfl_xor_sync(0xffffffffu, p, 1);
        p += __shfl_xor_sync(0xffffffffu, p, 2);   // quad = one head
        float eh = p * rscale;
        float mn = fmaxf(m, eh);
        float corr = __expf(m - mn);
        float wgt = __expf(eh - mn);
        s = s * corr + wgt;
        acc.x = acc.x * corr + v4.x * wgt;
        acc.y = acc.y * corr + v4.y * wgt;
        acc.z = acc.z * corr + v4.z * wgt;
        acc.w = acc.w * corr + v4.w * wgt;
        m = mn;
    }
    float inv = (s > 0.f) ? 1.f / s : 0.f;

    const float4 f4 = *(const float4*)(feat + (size_t)n * FDIM + lane * 4);
    float x0 = acc.x * inv + f4.x;
    float x1 = acc.y * inv + f4.y;
    float x2 = acc.z * inv + f4.z;
    float x3 = acc.w * inv + f4.w;

    float p = x0 + x1 + x2 + x3;
#pragma unroll
    for (int o = 16; o; o >>= 1) p += __shfl_xor_sync(0xffffffffu, p, o);
    float mu = p * (1.f / 128.f);
    float d0 = x0 - mu, d1 = x1 - mu, d2 = x2 - mu, d3 = x3 - mu;
    float q = d0 * d0 + d1 * d1 + d2 * d2 + d3 * d3;
#pragma unroll
    for (int o = 16; o; o >>= 1) q += __shfl_xor_sync(0xffffffffu, q, o);
    float rs = rsqrtf(q * (1.f / 128.f) + 1e-5f);

    const float4 gv = *(const float4*)(lng + lane * 4);
    const float4 lb = *(const float4*)(lnb + lane * 4);
    float y0 = d0 * rs * gv.x + lb.x;
    float y1 = d1 * rs * gv.y + lb.y;
    float y2 = d2 * rs * gv.z + lb.z;
    float y3 = d3 * rs * gv.w + lb.w;
    size_t base = (size_t)n * FDIM + lane * 4;
    *(float4*)(g_rst + base) = make_float4(y0, y1, y2, y3);

    unsigned h01, l01, h23, l23;
    split2(y0, y1, h01, l01);
    split2(y2, y3, h23, l23);
    size_t w = base >> 1;
    ((unsigned*)g_rst_h)[w] = h01;
    ((unsigned*)g_rst_h)[w + 1] = h23;
    ((unsigned*)g_rst_l)[w] = l01;
    ((unsigned*)g_rst_l)[w + 1] = l23;
}

// ---------------------------------------------------------------- launch
extern "C" void kernel_launch(void* const* d_in, const int* in_sizes, int n_in,
                              void* d_out, int out_size) {
    const float* feat = (const float*)d_in[0];
    const int* src = (const int*)d_in[1];
    const int* dst = (const int*)d_in[2];
    const float* Wq = (const float*)d_in[3];
    const float* Wk = (const float*)d_in[4];
    const float* Wv = (const float*)d_in[5];
    const float* ln1_g = (const float*)d_in[6];
    const float* ln1_b = (const float*)d_in[7];
    const float* W1 = (const float*)d_in[8];
    const float* b1 = (const float*)d_in[9];
    const float* pa = (const float*)d_in[10];
    const float* W2 = (const float*)d_in[11];
    const float* b2 = (const float*)d_in[12];
    float* out = (float*)d_out;

    const int MB128 = (NNODES + 127) / 128;  // 391

    // launch order: QKV mma at OUR index 3 == the profiled slot
    k_split_feat<<<(NNODES * FDIM / 2 + 255) / 256, 256>>>(feat);     // 0
    k_split_wall<<<(180224 + 255) / 256, 256>>>(Wq, Wk, Wv, W1, W2);  // 1
    k_zero_deg<<<SCAN_NB, 256>>>();                                   // 2
    k_gemm_qkv<<<dim3(3, MB128), 256>>>();                            // 3 <- ncu

    // CSR build
    k_hist<<<NEDGES / 256, 256>>>(dst);
    k_scan1<<<SCAN_NB, 256>>>();
    k_scan2<<<1, 256>>>();
    k_scan3<<<SCAN_NB, 256>>>();
    k_scatter<<<NEDGES / 256, 256>>>(dst);

    // attention aggregation + residual + LN1 (+ bf16 hi/lo split of rst)
    k_aggregate<<<(NNODES * 32 + 255) / 256, 256>>>(feat, src, ln1_g, ln1_b);

    // FFN (tensor cores)
    k_ffn1<<<dim3(DFF / 128, MB128), 256>>>(b1, pa);
    k_ffn2<<<dim3(1, MB128), 256>>>(b2);
    k_ln<<<(NNODES + 7) / 8, 256>>>(ln1_g, ln1_b, out);
}

// round 10
// speedup vs baseline: 1.0025x; 1.0025x over previous
#include <cuda_runtime.h>
#include <cuda_bf16.h>
#include <math.h>

// ---------------------------------------------------------------------------
// GAT layer (round 10): R8 + ldmatrix fragment loading in the GEMM mainloop.
// ncu R8/R9: tensor pipe only 40% active; 48 scalar LDS.32 per warp per
// k-step drain the pipe -> replace with 12 ldmatrix.x4 (conflict-free at
// 48B row stride; lane mapping == mma fragment convention).
// ---------------------------------------------------------------------------

#define NNODES 50000
#define NEDGES 640000
#define FDIM   128
#define DFF    512
#define SCAN_NB ((NNODES + 255) / 256)   // 196
#define RSTR   12                        // SMEM row stride in u32 words (48B)
#define ARRB   (128 * RSTR * 4)          // bytes per smem array (6144)

// fp32 scratch
__device__ __align__(16) float g_q[NNODES * FDIM];
__device__ __align__(16) float g_k[NNODES * FDIM];
__device__ __align__(16) float g_v[NNODES * FDIM];
__device__ __align__(16) float g_rst[NNODES * FDIM];
__device__ __align__(16) float g_x[NNODES * FDIM];
// bf16 hi/lo activations
__device__ __align__(16) __nv_bfloat16 g_feat_h[NNODES * FDIM];
__device__ __align__(16) __nv_bfloat16 g_feat_l[NNODES * FDIM];
__device__ __align__(16) __nv_bfloat16 g_rst_h[NNODES * FDIM];
__device__ __align__(16) __nv_bfloat16 g_rst_l[NNODES * FDIM];
__device__ __align__(16) __nv_bfloat16 g_hbuf_h[NNODES * DFF];
__device__ __align__(16) __nv_bfloat16 g_hbuf_l[NNODES * DFF];
// transposed split weights: Wt[n][k] bf16 hi/lo
__device__ __align__(16) __nv_bfloat16 g_Wqt_h[FDIM * FDIM];
__device__ __align__(16) __nv_bfloat16 g_Wqt_l[FDIM * FDIM];
__device__ __align__(16) __nv_bfloat16 g_Wkt_h[FDIM * FDIM];
__device__ __align__(16) __nv_bfloat16 g_Wkt_l[FDIM * FDIM];
__device__ __align__(16) __nv_bfloat16 g_Wvt_h[FDIM * FDIM];
__device__ __align__(16) __nv_bfloat16 g_Wvt_l[FDIM * FDIM];
__device__ __align__(16) __nv_bfloat16 g_W1t_h[DFF * FDIM];
__device__ __align__(16) __nv_bfloat16 g_W1t_l[DFF * FDIM];
__device__ __align__(16) __nv_bfloat16 g_W2t_h[FDIM * DFF];
__device__ __align__(16) __nv_bfloat16 g_W2t_l[FDIM * DFF];
// CSR
__device__ int g_deg[NNODES];
__device__ int g_off[NNODES + 1];
__device__ int g_eid[NEDGES];
__device__ int g_bsum[256];

// ---------------------------------------------------------------- helpers
__device__ __forceinline__ void split2(float a, float b, unsigned& h,
                                       unsigned& l) {
    __nv_bfloat16 ha = __float2bfloat16_rn(a);
    __nv_bfloat16 hb = __float2bfloat16_rn(b);
    __nv_bfloat16 la = __float2bfloat16_rn(a - __bfloat162float(ha));
    __nv_bfloat16 lb = __float2bfloat16_rn(b - __bfloat162float(hb));
    __nv_bfloat162 hh, ll;
    hh.x = ha; hh.y = hb;
    ll.x = la; ll.y = lb;
    h = *(unsigned*)&hh;
    l = *(unsigned*)&ll;
}

#define MMA_BF16(C, A0, A1, A2, A3, B0, B1)                                   \
    asm volatile(                                                             \
        "mma.sync.aligned.m16n8k16.row.col.f32.bf16.bf16.f32 "                \
        "{%0,%1,%2,%3}, {%4,%5,%6,%7}, {%8,%9}, {%0,%1,%2,%3};"               \
        : "+f"((C)[0]), "+f"((C)[1]), "+f"((C)[2]), "+f"((C)[3])              \
        : "r"(A0), "r"(A1), "r"(A2), "r"(A3), "r"(B0), "r"(B1));

#define LDSM_X4(r0, r1, r2, r3, addr)                                         \
    asm volatile(                                                             \
        "ldmatrix.sync.aligned.m8n8.x4.shared.b16 {%0,%1,%2,%3}, [%4];"       \
        : "=r"(r0), "=r"(r1), "=r"(r2), "=r"(r3)                              \
        : "r"(addr));

#define CPASYNC16(dst, src, sz)                                               \
    asm volatile("cp.async.cg.shared.global [%0], [%1], 16, %2;" ::           \
                     "r"(dst), "l"(src), "r"(sz))
#define CP_COMMIT() asm volatile("cp.async.commit_group;")
#define CP_WAIT1() asm volatile("cp.async.wait_group 1;")
#define CP_WAIT0() asm volatile("cp.async.wait_group 0;")

// one fused kernel: transpose+split all 5 weight matrices to bf16 hi/lo.
__global__ void k_split_wall(const float* __restrict__ Wq,
                             const float* __restrict__ Wk,
                             const float* __restrict__ Wv,
                             const float* __restrict__ W1,
                             const float* __restrict__ W2) {
    int i = blockIdx.x * blockDim.x + threadIdx.x;
    const float* in;
    __nv_bfloat16 *oh, *ol;
    int idx, K, N;
    if (i < 16384) {
        in = Wq; oh = g_Wqt_h; ol = g_Wqt_l; idx = i; K = FDIM; N = FDIM;
    } else if (i < 32768) {
        in = Wk; oh = g_Wkt_h; ol = g_Wkt_l; idx = i - 16384; K = FDIM; N = FDIM;
    } else if (i < 49152) {
        in = Wv; oh = g_Wvt_h; ol = g_Wvt_l; idx = i - 32768; K = FDIM; N = FDIM;
    } else if (i < 114688) {
        in = W1; oh = g_W1t_h; ol = g_W1t_l; idx = i - 49152; K = FDIM; N = DFF;
    } else if (i < 180224) {
        in = W2; oh = g_W2t_h; ol = g_W2t_l; idx = i - 114688; K = DFF; N = FDIM;
    } else {
        return;
    }
    int n = idx / K, k = idx - n * K;
    float x = in[(size_t)k * N + n];
    __nv_bfloat16 h = __float2bfloat16_rn(x);
    oh[idx] = h;
    ol[idx] = __float2bfloat16_rn(x - __bfloat162float(h));
}

// split feat (fp32, row-major) -> g_feat_h / g_feat_l
__global__ void k_split_feat(const float* __restrict__ in) {
    int i = blockIdx.x * blockDim.x + threadIdx.x;   // pair index
    if (i >= NNODES * FDIM / 2) return;
    float2 v = ((const float2*)in)[i];
    unsigned h, l;
    split2(v.x, v.y, h, l);
    ((unsigned*)g_feat_h)[i] = h;
    ((unsigned*)g_feat_l)[i] = l;
}

// ---------------------------------------------------------------- CSR build
__global__ void k_zero_deg() {
    int i = blockIdx.x * blockDim.x + threadIdx.x;
    if (i < NNODES) g_deg[i] = 0;
}
__global__ void k_hist(const int* __restrict__ dst) {
    int e = blockIdx.x * blockDim.x + threadIdx.x;
    if (e < NEDGES) atomicAdd(&g_deg[dst[e]], 1);
}
__global__ void k_scan1() {
    __shared__ int s[256];
    int b = blockIdx.x, t = threadIdx.x;
    int i = b * 256 + t;
    int v = (i < NNODES) ? g_deg[i] : 0;
    s[t] = v;
    __syncthreads();
#pragma unroll
    for (int off = 1; off < 256; off <<= 1) {
        int add = (t >= off) ? s[t - off] : 0;
        __syncthreads();
        s[t] += add;
        __syncthreads();
    }
    if (i < NNODES) g_off[i + 1] = s[t];
    if (t == 255) g_bsum[b] = s[t];
}
__global__ void k_scan2() {
    __shared__ int s[256];
    int t = threadIdx.x;
    int v = (t < SCAN_NB) ? g_bsum[t] : 0;
    s[t] = v;
    __syncthreads();
#pragma unroll
    for (int off = 1; off < 256; off <<= 1) {
        int add = (t >= off) ? s[t - off] : 0;
        __syncthreads();
        s[t] += add;
        __syncthreads();
    }
    if (t < SCAN_NB) g_bsum[t] = s[t] - v;
}
// scan3 also re-zeros g_deg for the scatter pass
__global__ void k_scan3() {
    int b = blockIdx.x, t = threadIdx.x;
    int i = b * 256 + t;
    if (i < NNODES) {
        g_off[i + 1] += g_bsum[b];
        g_deg[i] = 0;
    }
    if (i == 0) g_off[0] = 0;
}
__global__ void k_scatter(const int* __restrict__ dst) {
    int e = blockIdx.x * blockDim.x + threadIdx.x;
    if (e < NEDGES) {
        int d = dst[e];
        int pos = g_off[d] + atomicAdd(&g_deg[d], 1);
        g_eid[pos] = e;
    }
}

// ------------------------------------------------- MMA GEMM core (pipelined)
// BM=128, BN=128, BK=16, 256 threads = 8 warps (2 M x 4 N), warp tile 64x32.
// Fragments loaded via ldmatrix.x4 (12 per warp per k-step).
#define GEMM_MMA_BF(AHI, ALO, BTHI, BTLO, KTOT, COL0)                          \
    float acc[4][4][4];                                                       \
    _Pragma("unroll") for (int a_ = 0; a_ < 4; a_++)                          \
        _Pragma("unroll") for (int b_ = 0; b_ < 4; b_++)                      \
            _Pragma("unroll") for (int c_ = 0; c_ < 4; c_++)                  \
                acc[a_][b_][c_] = 0.f;                                        \
    __shared__ unsigned sm[2][4][128 * RSTR];                                 \
    const int tid = threadIdx.x;                                              \
    const int lane = tid & 31, wid = tid >> 5;                                \
    const int wm = wid >> 2, wn = wid & 3;                                    \
    const int g = lane >> 2, tk = lane & 3;                                   \
    const int row0 = blockIdx.y * 128;                                        \
    const int lr = tid >> 1, lh = tid & 1;                                    \
    int arow = row0 + lr;                                                     \
    const unsigned okA = (arow < NNODES) ? 16u : 0u;                          \
    if (arow >= NNODES) arow = NNODES - 1;                                    \
    const int brow = (COL0) + lr;                                             \
    const __nv_bfloat16* gsrc[4] = {                                          \
        (AHI) + (size_t)arow * (KTOT) + lh * 8,                               \
        (ALO) + (size_t)arow * (KTOT) + lh * 8,                               \
        (BTHI) + (size_t)brow * (KTOT) + lh * 8,                              \
        (BTLO) + (size_t)brow * (KTOT) + lh * 8};                             \
    const unsigned szs[4] = {okA, okA, 16u, 16u};                             \
    const unsigned smraw = (unsigned)__cvta_generic_to_shared(&sm[0][0][0]);  \
    const unsigned smbase = smraw + (unsigned)((lr * RSTR + lh * 4) * 4);     \
    /* ldmatrix per-lane addresses (offsets within one array) */              \
    const unsigned aoff = (unsigned)((wm * 64 + (lane & 7) +                  \
                                      ((lane >> 3) & 1) * 8) * 48 +           \
                                     (lane >> 4) * 16);                       \
    const unsigned boff = (unsigned)((wn * 32 + ((lane >> 4) & 1) * 8 +       \
                                      (lane & 7)) * 48 +                      \
                                     ((lane >> 3) & 1) * 16);                 \
    const int NT = (KTOT) / 16;                                               \
    _Pragma("unroll") for (int a_ = 0; a_ < 4; a_++)                          \
        CPASYNC16(smbase + a_ * ARRB, gsrc[a_], szs[a_]);                     \
    CP_COMMIT();                                                              \
    for (int kt = 0; kt < NT; kt++) {                                         \
        if (kt + 1 < NT) {                                                    \
            unsigned sb = smbase + ((kt + 1) & 1) * (4 * ARRB);               \
            _Pragma("unroll") for (int a_ = 0; a_ < 4; a_++)                  \
                CPASYNC16(sb + a_ * ARRB, gsrc[a_] + (kt + 1) * 16,           \
                          szs[a_]);                                           \
            CP_COMMIT();                                                      \
            CP_WAIT1();                                                       \
        } else {                                                              \
            CP_WAIT0();                                                       \
        }                                                                     \
        __syncthreads();                                                      \
        const unsigned st = smraw + (kt & 1) * (4 * ARRB);                    \
        unsigned ah[4][4], al[4][4], bh[4][2], bl[4][2];                      \
        _Pragma("unroll") for (int mt = 0; mt < 4; mt++) {                    \
            LDSM_X4(ah[mt][0], ah[mt][1], ah[mt][2], ah[mt][3],               \
                    st + 0 * ARRB + aoff + mt * 768);                         \
            LDSM_X4(al[mt][0], al[mt][1], al[mt][2], al[mt][3],               \
                    st + 1 * ARRB + aoff + mt * 768);                         \
        }                                                                     \
        _Pragma("unroll") for (int p = 0; p < 2; p++) {                       \
            LDSM_X4(bh[2 * p][0], bh[2 * p][1], bh[2 * p + 1][0],             \
                    bh[2 * p + 1][1], st + 2 * ARRB + boff + p * 768);        \
            LDSM_X4(bl[2 * p][0], bl[2 * p][1], bl[2 * p + 1][0],             \
                    bl[2 * p + 1][1], st + 3 * ARRB + boff + p * 768);        \
        }                                                                     \
        _Pragma("unroll") for (int mt = 0; mt < 4; mt++)                      \
            _Pragma("unroll") for (int nt = 0; nt < 4; nt++)                  \
                MMA_BF16(acc[mt][nt], ah[mt][0], ah[mt][1], ah[mt][2],        \
                         ah[mt][3], bh[nt][0], bh[nt][1]);                    \
        _Pragma("unroll") for (int mt = 0; mt < 4; mt++)                      \
            _Pragma("unroll") for (int nt = 0; nt < 4; nt++)                  \
                MMA_BF16(acc[mt][nt], ah[mt][0], ah[mt][1], ah[mt][2],        \
                         ah[mt][3], bl[nt][0], bl[nt][1]);                    \
        _Pragma("unroll") for (int mt = 0; mt < 4; mt++)                      \
            _Pragma("unroll") for (int nt = 0; nt < 4; nt++)                  \
                MMA_BF16(acc[mt][nt], al[mt][0], al[mt][1], al[mt][2],        \
                         al[mt][3], bh[nt][0], bh[nt][1]);                    \
        __syncthreads();                                                      \
    }

// QKV: grid (3, 391); blockIdx.x selects {q,k,v}
__global__ __launch_bounds__(256, 1) void k_gemm_qkv() {
    const int m = blockIdx.x;
    const __nv_bfloat16* Bh = (m == 0) ? g_Wqt_h : (m == 1) ? g_Wkt_h : g_Wvt_h;
    const __nv_bfloat16* Bl = (m == 0) ? g_Wqt_l : (m == 1) ? g_Wkt_l : g_Wvt_l;
    float* C = (m == 0) ? g_q : (m == 1) ? g_k : g_v;
    GEMM_MMA_BF(g_feat_h, g_feat_l, Bh, Bl, FDIM, 0)
#pragma unroll
    for (int mt = 0; mt < 4; mt++) {
#pragma unroll
        for (int nt = 0; nt < 4; nt++) {
            int row = row0 + wm * 64 + mt * 16 + g;
            int col = wn * 32 + nt * 8 + tk * 2;
#pragma unroll
            for (int hf = 0; hf < 2; hf++) {
                int r = row + hf * 8;
                if (r >= NNODES) continue;
                *(float2*)(C + (size_t)r * FDIM + col) =
                    make_float2(acc[mt][nt][hf * 2 + 0],
                                acc[mt][nt][hf * 2 + 1]);
            }
        }
    }
}

// FFN1: hbuf(hi/lo bf16) = PReLU(rst @ W1 + b1) ; grid (4, 391)
__global__ __launch_bounds__(256, 1) void k_ffn1(const float* __restrict__ b1,
                                                 const float* __restrict__ pa) {
    const int col0 = blockIdx.x * 128;
    GEMM_MMA_BF(g_rst_h, g_rst_l, g_W1t_h, g_W1t_l, FDIM, col0)
#pragma unroll
    for (int mt = 0; mt < 4; mt++) {
#pragma unroll
        for (int nt = 0; nt < 4; nt++) {
            int row = row0 + wm * 64 + mt * 16 + g;
            int col = col0 + wn * 32 + nt * 8 + tk * 2;
            float bb0 = b1[col], bb1 = b1[col + 1];
            float pa0 = pa[col], pa1 = pa[col + 1];
#pragma unroll
            for (int hf = 0; hf < 2; hf++) {
                int r = row + hf * 8;
                if (r >= NNODES) continue;
                float h0 = acc[mt][nt][hf * 2 + 0] + bb0;
                float h1 = acc[mt][nt][hf * 2 + 1] + bb1;
                h0 = (h0 >= 0.f) ? h0 : pa0 * h0;
                h1 = (h1 >= 0.f) ? h1 : pa1 * h1;
                unsigned hw, lw;
                split2(h0, h1, hw, lw);
                size_t w = ((size_t)r * DFF + col) >> 1;
                ((unsigned*)g_hbuf_h)[w] = hw;
                ((unsigned*)g_hbuf_l)[w] = lw;
            }
        }
    }
}

// FFN2: g_x = hbuf @ W2 + b2 + rst ; grid (1, 391)
__global__ __launch_bounds__(256, 1) void k_ffn2(const float* __restrict__ b2) {
    GEMM_MMA_BF(g_hbuf_h, g_hbuf_l, g_W2t_h, g_W2t_l, DFF, 0)
#pragma unroll
    for (int mt = 0; mt < 4; mt++) {
#pragma unroll
        for (int nt = 0; nt < 4; nt++) {
            int row = row0 + wm * 64 + mt * 16 + g;
            int col = wn * 32 + nt * 8 + tk * 2;
            float bb0 = b2[col], bb1 = b2[col + 1];
#pragma unroll
            for (int hf = 0; hf < 2; hf++) {
                int r = row + hf * 8;
                if (r >= NNODES) continue;
                float2 rv = *(const float2*)(g_rst + (size_t)r * FDIM + col);
                *(float2*)(g_x + (size_t)r * FDIM + col) =
                    make_float2(acc[mt][nt][hf * 2 + 0] + bb0 + rv.x,
                                acc[mt][nt][hf * 2 + 1] + bb1 + rv.y);
            }
        }
    }
}

// final LN over g_x -> out ; one warp per row
__global__ __launch_bounds__(256) void k_ln(const float* __restrict__ lng,
                                            const float* __restrict__ lnb,
                                            float* __restrict__ out) {
    int n = blockIdx.x * 8 + (threadIdx.x >> 5);
    int lane = threadIdx.x & 31;
    if (n >= NNODES) return;
    float4 x = *(const float4*)(g_x + (size_t)n * FDIM + lane * 4);
    float p = x.x + x.y + x.z + x.w;
#pragma unroll
    for (int o = 16; o; o >>= 1) p += __shfl_xor_sync(0xffffffffu, p, o);
    float mu = p * (1.f / 128.f);
    float d0 = x.x - mu, d1 = x.y - mu, d2 = x.z - mu, d3 = x.w - mu;
    float q = d0 * d0 + d1 * d1 + d2 * d2 + d3 * d3;
#pragma unroll
    for (int o = 16; o; o >>= 1) q += __shfl_xor_sync(0xffffffffu, q, o);
    float rs = rsqrtf(q * (1.f / 128.f) + 1e-5f);
    const float4 gv = *(const float4*)(lng + lane * 4);
    const float4 lb = *(const float4*)(lnb + lane * 4);
    *(float4*)(out + (size_t)n * FDIM + lane * 4) =
        make_float4(d0 * rs * gv.x + lb.x, d1 * rs * gv.y + lb.y,
                    d2 * rs * gv.z + lb.z, d3 * rs * gv.w + lb.w);
}

// --------------------------------------------- attention aggregate + LN1
__global__ __launch_bounds__(256) void k_aggregate(
    const float* __restrict__ feat, const int* __restrict__ src,
    const float* __restrict__ lng, const float* __restrict__ lnb) {
    int n = (blockIdx.x * blockDim.x + threadIdx.x) >> 5;
    int lane = threadIdx.x & 31;
    if (n >= NNODES) return;

    const float4 q4 = *(const float4*)(g_q + (size_t)n * FDIM + lane * 4);
    float4 acc = make_float4(0.f, 0.f, 0.f, 0.f);
    float m = -INFINITY, s = 0.f;
    const float rscale = 0.08838834764831845f;   // 1/sqrt(128)

    int beg = g_off[n], end = g_off[n + 1];
    for (int idx = beg; idx < end; ++idx) {
        int e = g_eid[idx];
        int sn = src[e];
        const float4 k4 = *(const float4*)(g_k + (size_t)sn * FDIM + lane * 4);
        const float4 v4 = *(const float4*)(g_v + (size_t)sn * FDIM + lane * 4);
        float p = k4.x * q4.x + k4.y * q4.y + k4.z * q4.z + k4.w * q4.w;
        p += __shfl_xor_sync(0xffffffffu, p, 1);
        p += __shfl_xor_sync(0xffffffffu, p, 2);   // quad = one head
        float eh = p * rscale;
        float mn = fmaxf(m, eh);
        float corr = __expf(m - mn);
        float wgt = __expf(eh - mn);
        s = s * corr + wgt;
        acc.x = acc.x * corr + v4.x * wgt;
        acc.y = acc.y * corr + v4.y * wgt;
        acc.z = acc.z * corr + v4.z * wgt;
        acc.w = acc.w * corr + v4.w * wgt;
        m = mn;
    }
    float inv = (s > 0.f) ? 1.f / s : 0.f;

    const float4 f4 = *(const float4*)(feat + (size_t)n * FDIM + lane * 4);
    float x0 = acc.x * inv + f4.x;
    float x1 = acc.y * inv + f4.y;
    float x2 = acc.z * inv + f4.z;
    float x3 = acc.w * inv + f4.w;

    float p = x0 + x1 + x2 + x3;
#pragma unroll
    for (int o = 16; o; o >>= 1) p += __shfl_xor_sync(0xffffffffu, p, o);
    float mu = p * (1.f / 128.f);
    float d0 = x0 - mu, d1 = x1 - mu, d2 = x2 - mu, d3 = x3 - mu;
    float q = d0 * d0 + d1 * d1 + d2 * d2 + d3 * d3;
#pragma unroll
    for (int o = 16; o; o >>= 1) q += __shfl_xor_sync(0xffffffffu, q, o);
    float rs = rsqrtf(q * (1.f / 128.f) + 1e-5f);

    const float4 gv = *(const float4*)(lng + lane * 4);
    const float4 lb = *(const float4*)(lnb + lane * 4);
    float y0 = d0 * rs * gv.x + lb.x;
    float y1 = d1 * rs * gv.y + lb.y;
    float y2 = d2 * rs * gv.z + lb.z;
    float y3 = d3 * rs * gv.w + lb.w;
    size_t base = (size_t)n * FDIM + lane * 4;
    *(float4*)(g_rst + base) = make_float4(y0, y1, y2, y3);

    unsigned h01, l01, h23, l23;
    split2(y0, y1, h01, l01);
    split2(y2, y3, h23, l23);
    size_t w = base >> 1;
    ((unsigned*)g_rst_h)[w] = h01;
    ((unsigned*)g_rst_h)[w + 1] = h23;
    ((unsigned*)g_rst_l)[w] = l01;
    ((unsigned*)g_rst_l)[w + 1] = l23;
}

// ---------------------------------------------------------------- launch
extern "C" void kernel_launch(void* const* d_in, const int* in_sizes, int n_in,
                              void* d_out, int out_size) {
    const float* feat = (const float*)d_in[0];
    const int* src = (const int*)d_in[1];
    const int* dst = (const int*)d_in[2];
    const float* Wq = (const float*)d_in[3];
    const float* Wk = (const float*)d_in[4];
    const float* Wv = (const float*)d_in[5];
    const float* ln1_g = (const float*)d_in[6];
    const float* ln1_b = (const float*)d_in[7];
    const float* W1 = (const float*)d_in[8];
    const float* b1 = (const float*)d_in[9];
    const float* pa = (const float*)d_in[10];
    const float* W2 = (const float*)d_in[11];
    const float* b2 = (const float*)d_in[12];
    float* out = (float*)d_out;

    const int MB128 = (NNODES + 127) / 128;  // 391

    // launch order: QKV mma at OUR index 3 == the profiled slot
    k_split_feat<<<(NNODES * FDIM / 2 + 255) / 256, 256>>>(feat);     // 0
    k_split_wall<<<(180224 + 255) / 256, 256>>>(Wq, Wk, Wv, W1, W2);  // 1
    k_zero_deg<<<SCAN_NB, 256>>>();                                   // 2
    k_gemm_qkv<<<dim3(3, MB128), 256>>>();                            // 3 <- ncu

    // CSR build
    k_hist<<<NEDGES / 256, 256>>>(dst);
    k_scan1<<<SCAN_NB, 256>>>();
    k_scan2<<<1, 256>>>();
    k_scan3<<<SCAN_NB, 256>>>();
    k_scatter<<<NEDGES / 256, 256>>>(dst);

    // attention aggregation + residual + LN1 (+ bf16 hi/lo split of rst)
    k_aggregate<<<(NNODES * 32 + 255) / 256, 256>>>(feat, src, ln1_g, ln1_b);

    // FFN (tensor cores)
    k_ffn1<<<dim3(DFF / 128, MB128), 256>>>(b1, pa);
    k_ffn2<<<dim3(1, MB128), 256>>>(b2);
    k_ln<<<(NNODES + 7) / 8, 256>>>(ln1_g, ln1_b, out);
}

// round 12
// speedup vs baseline: 1.2335x; 1.2304x over previous
#include <cuda_runtime.h>
#include <cuda_fp16.h>
#include <math.h>

// ---------------------------------------------------------------------------
// GAT layer (round 12): R8 structure, GEMMs switched to fp16 split-precision
// with TWO mma passes: C ~= A_f16 * Bh + A_f16 * Bl  (B = fp16 hi+lo).
// Dropped term == A's fp16 rounding -> predicted rel_err ~3e-4 (model
// validated at bf16-3pass: predicted 3.8e-6 vs measured 2.8e-6).
// tcgen05 unavailable: harness targets compute_103 (no 'a' features).
// ---------------------------------------------------------------------------

#define NNODES 50000
#define NEDGES 640000
#define FDIM   128
#define DFF    512
#define SCAN_NB ((NNODES + 255) / 256)   // 196
#define RSTR   12                        // SMEM row stride in u32 words (48B)
#define ARRW   (128 * RSTR)              // u32 words per smem array

// fp32 scratch
__device__ __align__(16) float g_q[NNODES * FDIM];
__device__ __align__(16) float g_k[NNODES * FDIM];
__device__ __align__(16) float g_v[NNODES * FDIM];
__device__ __align__(16) float g_rst[NNODES * FDIM];
__device__ __align__(16) float g_x[NNODES * FDIM];
// fp16 activations (A operands)
__device__ __align__(16) __half g_feat16[NNODES * FDIM];
__device__ __align__(16) __half g_rst16[NNODES * FDIM];
__device__ __align__(16) __half g_hbuf16[NNODES * DFF];
// transposed split weights: Wt[n][k] fp16 hi/lo
__device__ __align__(16) __half g_Wqt_h[FDIM * FDIM];
__device__ __align__(16) __half g_Wqt_l[FDIM * FDIM];
__device__ __align__(16) __half g_Wkt_h[FDIM * FDIM];
__device__ __align__(16) __half g_Wkt_l[FDIM * FDIM];
__device__ __align__(16) __half g_Wvt_h[FDIM * FDIM];
__device__ __align__(16) __half g_Wvt_l[FDIM * FDIM];
__device__ __align__(16) __half g_W1t_h[DFF * FDIM];
__device__ __align__(16) __half g_W1t_l[DFF * FDIM];
__device__ __align__(16) __half g_W2t_h[FDIM * DFF];
__device__ __align__(16) __half g_W2t_l[FDIM * DFF];
// CSR
__device__ int g_deg[NNODES];
__device__ int g_off[NNODES + 1];
__device__ int g_eid[NEDGES];
__device__ int g_bsum[256];

// ---------------------------------------------------------------- helpers
__device__ __forceinline__ unsigned pkh2(float a, float b) {
    __half2 t = __floats2half2_rn(a, b);
    return *(unsigned*)&t;
}

#define MMA_F16(C, A0, A1, A2, A3, B0, B1)                                    \
    asm volatile(                                                             \
        "mma.sync.aligned.m16n8k16.row.col.f32.f16.f16.f32 "                  \
        "{%0,%1,%2,%3}, {%4,%5,%6,%7}, {%8,%9}, {%0,%1,%2,%3};"               \
        : "+f"((C)[0]), "+f"((C)[1]), "+f"((C)[2]), "+f"((C)[3])              \
        : "r"(A0), "r"(A1), "r"(A2), "r"(A3), "r"(B0), "r"(B1));

#define CPASYNC16(dst, src, sz)                                               \
    asm volatile("cp.async.cg.shared.global [%0], [%1], 16, %2;" ::           \
                     "r"(dst), "l"(src), "r"(sz))
#define CP_COMMIT() asm volatile("cp.async.commit_group;")
#define CP_WAIT1() asm volatile("cp.async.wait_group 1;")
#define CP_WAIT0() asm volatile("cp.async.wait_group 0;")

// one fused kernel: transpose+split all 5 weight matrices to fp16 hi/lo.
__global__ void k_split_wall(const float* __restrict__ Wq,
                             const float* __restrict__ Wk,
                             const float* __restrict__ Wv,
                             const float* __restrict__ W1,
                             const float* __restrict__ W2) {
    int i = blockIdx.x * blockDim.x + threadIdx.x;
    const float* in;
    __half *oh, *ol;
    int idx, K, N;
    if (i < 16384) {
        in = Wq; oh = g_Wqt_h; ol = g_Wqt_l; idx = i; K = FDIM; N = FDIM;
    } else if (i < 32768) {
        in = Wk; oh = g_Wkt_h; ol = g_Wkt_l; idx = i - 16384; K = FDIM; N = FDIM;
    } else if (i < 49152) {
        in = Wv; oh = g_Wvt_h; ol = g_Wvt_l; idx = i - 32768; K = FDIM; N = FDIM;
    } else if (i < 114688) {
        in = W1; oh = g_W1t_h; ol = g_W1t_l; idx = i - 49152; K = FDIM; N = DFF;
    } else if (i < 180224) {
        in = W2; oh = g_W2t_h; ol = g_W2t_l; idx = i - 114688; K = DFF; N = FDIM;
    } else {
        return;
    }
    int n = idx / K, k = idx - n * K;
    float x = in[(size_t)k * N + n];
    __half h = __float2half_rn(x);
    oh[idx] = h;
    ol[idx] = __float2half_rn(x - __half2float(h));
}

// feat (fp32) -> g_feat16 fp16
__global__ void k_split_feat(const float* __restrict__ in) {
    int i = blockIdx.x * blockDim.x + threadIdx.x;   // pair index
    if (i >= NNODES * FDIM / 2) return;
    float2 v = ((const float2*)in)[i];
    ((unsigned*)g_feat16)[i] = pkh2(v.x, v.y);
}

// ---------------------------------------------------------------- CSR build
__global__ void k_zero_deg() {
    int i = blockIdx.x * blockDim.x + threadIdx.x;
    if (i < NNODES) g_deg[i] = 0;
}
__global__ void k_hist(const int* __restrict__ dst) {
    int e = blockIdx.x * blockDim.x + threadIdx.x;
    if (e < NEDGES) atomicAdd(&g_deg[dst[e]], 1);
}
__global__ void k_scan1() {
    __shared__ int s[256];
    int b = blockIdx.x, t = threadIdx.x;
    int i = b * 256 + t;
    int v = (i < NNODES) ? g_deg[i] : 0;
    s[t] = v;
    __syncthreads();
#pragma unroll
    for (int off = 1; off < 256; off <<= 1) {
        int add = (t >= off) ? s[t - off] : 0;
        __syncthreads();
        s[t] += add;
        __syncthreads();
    }
    if (i < NNODES) g_off[i + 1] = s[t];
    if (t == 255) g_bsum[b] = s[t];
}
__global__ void k_scan2() {
    __shared__ int s[256];
    int t = threadIdx.x;
    int v = (t < SCAN_NB) ? g_bsum[t] : 0;
    s[t] = v;
    __syncthreads();
#pragma unroll
    for (int off = 1; off < 256; off <<= 1) {
        int add = (t >= off) ? s[t - off] : 0;
        __syncthreads();
        s[t] += add;
        __syncthreads();
    }
    if (t < SCAN_NB) g_bsum[t] = s[t] - v;
}
// scan3 also re-zeros g_deg for the scatter pass
__global__ void k_scan3() {
    int b = blockIdx.x, t = threadIdx.x;
    int i = b * 256 + t;
    if (i < NNODES) {
        g_off[i + 1] += g_bsum[b];
        g_deg[i] = 0;
    }
    if (i == 0) g_off[0] = 0;
}
__global__ void k_scatter(const int* __restrict__ dst) {
    int e = blockIdx.x * blockDim.x + threadIdx.x;
    if (e < NEDGES) {
        int d = dst[e];
        int pos = g_off[d] + atomicAdd(&g_deg[d], 1);
        g_eid[pos] = e;
    }
}

// ------------------------------------------------- MMA GEMM core (pipelined)
// BM=128, BN=128, BK=16, 256 threads = 8 warps (2 M x 4 N), warp tile 64x32.
// A: fp16 [M,KTOT]. Bt: fp16 [N,KTOT] hi/lo, rows at COL0.
// SMEM: 2 stages x 3 arrays (A,Bh,Bl) x 128 rows x RSTR u32 words.
// 2 mma passes per k-step: A*Bh then A*Bl.
#define GEMM_MMA_H(APTR, BTHI, BTLO, KTOT, COL0)                               \
    float acc[4][4][4];                                                       \
    _Pragma("unroll") for (int a_ = 0; a_ < 4; a_++)                          \
        _Pragma("unroll") for (int b_ = 0; b_ < 4; b_++)                      \
            _Pragma("unroll") for (int c_ = 0; c_ < 4; c_++)                  \
                acc[a_][b_][c_] = 0.f;                                        \
    __shared__ unsigned sm[2][3][ARRW];                                       \
    const int tid = threadIdx.x;                                              \
    const int lane = tid & 31, wid = tid >> 5;                                \
    const int wm = wid >> 2, wn = wid & 3;                                    \
    const int g = lane >> 2, tk = lane & 3;                                   \
    const int row0 = blockIdx.y * 128;                                        \
    const int lr = tid >> 1, lh = tid & 1;                                    \
    int arow = row0 + lr;                                                     \
    const unsigned okA = (arow < NNODES) ? 16u : 0u;                          \
    if (arow >= NNODES) arow = NNODES - 1;                                    \
    const int brow = (COL0) + lr;                                             \
    const __half* gsrc[3] = {(APTR) + (size_t)arow * (KTOT) + lh * 8,         \
                             (BTHI) + (size_t)brow * (KTOT) + lh * 8,         \
                             (BTLO) + (size_t)brow * (KTOT) + lh * 8};        \
    const unsigned szs[3] = {okA, 16u, 16u};                                  \
    const unsigned smbase =                                                   \
        (unsigned)__cvta_generic_to_shared(&sm[0][0][0]) +                    \
        (unsigned)((lr * RSTR + lh * 4) * 4);                                 \
    const int NT = (KTOT) / 16;                                               \
    _Pragma("unroll") for (int a_ = 0; a_ < 3; a_++)                          \
        CPASYNC16(smbase + a_ * (ARRW * 4), gsrc[a_], szs[a_]);               \
    CP_COMMIT();                                                              \
    for (int kt = 0; kt < NT; kt++) {                                         \
        if (kt + 1 < NT) {                                                    \
            unsigned sb = smbase + ((kt + 1) & 1) * (3 * ARRW * 4);           \
            _Pragma("unroll") for (int a_ = 0; a_ < 3; a_++)                  \
                CPASYNC16(sb + a_ * (ARRW * 4), gsrc[a_] + (kt + 1) * 16,     \
                          szs[a_]);                                           \
            CP_COMMIT();                                                      \
            CP_WAIT1();                                                       \
        } else {                                                              \
            CP_WAIT0();                                                       \
        }                                                                     \
        __syncthreads();                                                      \
        const unsigned* As = sm[kt & 1][0];                                   \
        const unsigned* Bs_h = sm[kt & 1][1];                                 \
        const unsigned* Bs_l = sm[kt & 1][2];                                 \
        unsigned ah[4][4], bh[4][2], bl[4][2];                                \
        _Pragma("unroll") for (int mt = 0; mt < 4; mt++) {                    \
            int br = wm * 64 + mt * 16;                                       \
            ah[mt][0] = As[(br + g) * RSTR + tk];                             \
            ah[mt][1] = As[(br + g + 8) * RSTR + tk];                         \
            ah[mt][2] = As[(br + g) * RSTR + tk + 4];                         \
            ah[mt][3] = As[(br + g + 8) * RSTR + tk + 4];                     \
        }                                                                     \
        _Pragma("unroll") for (int nt = 0; nt < 4; nt++) {                    \
            int bn = wn * 32 + nt * 8;                                        \
            bh[nt][0] = Bs_h[(bn + g) * RSTR + tk];                           \
            bh[nt][1] = Bs_h[(bn + g) * RSTR + tk + 4];                       \
            bl[nt][0] = Bs_l[(bn + g) * RSTR + tk];                           \
            bl[nt][1] = Bs_l[(bn + g) * RSTR + tk + 4];                       \
        }                                                                     \
        _Pragma("unroll") for (int mt = 0; mt < 4; mt++)                      \
            _Pragma("unroll") for (int nt = 0; nt < 4; nt++) {                \
                MMA_F16(acc[mt][nt], ah[mt][0], ah[mt][1], ah[mt][2],         \
                        ah[mt][3], bh[nt][0], bh[nt][1]);                     \
                MMA_F16(acc[mt][nt], ah[mt][0], ah[mt][1], ah[mt][2],         \
                        ah[mt][3], bl[nt][0], bl[nt][1]);                     \
            }                                                                 \
        __syncthreads();                                                      \
    }

// QKV: grid (3, 391); blockIdx.x selects {q,k,v}
__global__ __launch_bounds__(256, 1) void k_gemm_qkv() {
    const int m = blockIdx.x;
    const __half* Bh = (m == 0) ? g_Wqt_h : (m == 1) ? g_Wkt_h : g_Wvt_h;
    const __half* Bl = (m == 0) ? g_Wqt_l : (m == 1) ? g_Wkt_l : g_Wvt_l;
    float* C = (m == 0) ? g_q : (m == 1) ? g_k : g_v;
    GEMM_MMA_H(g_feat16, Bh, Bl, FDIM, 0)
#pragma unroll
    for (int mt = 0; mt < 4; mt++) {
#pragma unroll
        for (int nt = 0; nt < 4; nt++) {
            int row = row0 + wm * 64 + mt * 16 + g;
            int col = wn * 32 + nt * 8 + tk * 2;
#pragma unroll
            for (int hf = 0; hf < 2; hf++) {
                int r = row + hf * 8;
                if (r >= NNODES) continue;
                *(float2*)(C + (size_t)r * FDIM + col) =
                    make_float2(acc[mt][nt][hf * 2 + 0],
                                acc[mt][nt][hf * 2 + 1]);
            }
        }
    }
}

// FFN1: hbuf16 = PReLU(rst @ W1 + b1) ; grid (4, 391)
__global__ __launch_bounds__(256, 1) void k_ffn1(const float* __restrict__ b1,
                                                 const float* __restrict__ pa) {
    const int col0 = blockIdx.x * 128;
    GEMM_MMA_H(g_rst16, g_W1t_h, g_W1t_l, FDIM, col0)
#pragma unroll
    for (int mt = 0; mt < 4; mt++) {
#pragma unroll
        for (int nt = 0; nt < 4; nt++) {
            int row = row0 + wm * 64 + mt * 16 + g;
            int col = col0 + wn * 32 + nt * 8 + tk * 2;
            float bb0 = b1[col], bb1 = b1[col + 1];
            float pa0 = pa[col], pa1 = pa[col + 1];
#pragma unroll
            for (int hf = 0; hf < 2; hf++) {
                int r = row + hf * 8;
                if (r >= NNODES) continue;
                float h0 = acc[mt][nt][hf * 2 + 0] + bb0;
                float h1 = acc[mt][nt][hf * 2 + 1] + bb1;
                h0 = (h0 >= 0.f) ? h0 : pa0 * h0;
                h1 = (h1 >= 0.f) ? h1 : pa1 * h1;
                ((unsigned*)g_hbuf16)[((size_t)r * DFF + col) >> 1] =
                    pkh2(h0, h1);
            }
        }
    }
}

// FFN2: g_x = hbuf @ W2 + b2 + rst ; grid (1, 391)
__global__ __launch_bounds__(256, 1) void k_ffn2(const float* __restrict__ b2) {
    GEMM_MMA_H(g_hbuf16, g_W2t_h, g_W2t_l, DFF, 0)
#pragma unroll
    for (int mt = 0; mt < 4; mt++) {
#pragma unroll
        for (int nt = 0; nt < 4; nt++) {
            int row = row0 + wm * 64 + mt * 16 + g;
            int col = wn * 32 + nt * 8 + tk * 2;
            float bb0 = b2[col], bb1 = b2[col + 1];
#pragma unroll
            for (int hf = 0; hf < 2; hf++) {
                int r = row + hf * 8;
                if (r >= NNODES) continue;
                float2 rv = *(const float2*)(g_rst + (size_t)r * FDIM + col);
                *(float2*)(g_x + (size_t)r * FDIM + col) =
                    make_float2(acc[mt][nt][hf * 2 + 0] + bb0 + rv.x,
                                acc[mt][nt][hf * 2 + 1] + bb1 + rv.y);
            }
        }
    }
}

// final LN over g_x -> out ; one warp per row
__global__ __launch_bounds__(256) void k_ln(const float* __restrict__ lng,
                                            const float* __restrict__ lnb,
                                            float* __restrict__ out) {
    int n = blockIdx.x * 8 + (threadIdx.x >> 5);
    int lane = threadIdx.x & 31;
    if (n >= NNODES) return;
    float4 x = *(const float4*)(g_x + (size_t)n * FDIM + lane * 4);
    float p = x.x + x.y + x.z + x.w;
#pragma unroll
    for (int o = 16; o; o >>= 1) p += __shfl_xor_sync(0xffffffffu, p, o);
    float mu = p * (1.f / 128.f);
    float d0 = x.x - mu, d1 = x.y - mu, d2 = x.z - mu, d3 = x.w - mu;
    float q = d0 * d0 + d1 * d1 + d2 * d2 + d3 * d3;
#pragma unroll
    for (int o = 16; o; o >>= 1) q += __shfl_xor_sync(0xffffffffu, q, o);
    float rs = rsqrtf(q * (1.f / 128.f) + 1e-5f);
    const float4 gv = *(const float4*)(lng + lane * 4);
    const float4 lb = *(const float4*)(lnb + lane * 4);
    *(float4*)(out + (size_t)n * FDIM + lane * 4) =
        make_float4(d0 * rs * gv.x + lb.x, d1 * rs * gv.y + lb.y,
                    d2 * rs * gv.z + lb.z, d3 * rs * gv.w + lb.w);
}

// --------------------------------------------- attention aggregate + LN1
// one warp per dst node; online softmax per head (lane quad = head).
__global__ __launch_bounds__(256) void k_aggregate(
    const float* __restrict__ feat, const int* __restrict__ src,
    const float* __restrict__ lng, const float* __restrict__ lnb) {
    int n = (blockIdx.x * blockDim.x + threadIdx.x) >> 5;
    int lane = threadIdx.x & 31;
    if (n >= NNODES) return;

    const float4 q4 = *(const float4*)(g_q + (size_t)n * FDIM + lane * 4);
    float4 acc = make_float4(0.f, 0.f, 0.f, 0.f);
    float m = -INFINITY, s = 0.f;
    const float rscale = 0.08838834764831845f;   // 1/sqrt(128)

    int beg = g_off[n], end = g_off[n + 1];
    for (int idx = beg; idx < end; ++idx) {
        int e = g_eid[idx];
        int sn = src[e];
        const float4 k4 = *(const float4*)(g_k + (size_t)sn * FDIM + lane * 4);
        const float4 v4 = *(const float4*)(g_v + (size_t)sn * FDIM + lane * 4);
        float p = k4.x * q4.x + k4.y * q4.y + k4.z * q4.z + k4.w * q4.w;
        p += __shfl_xor_sync(0xffffffffu, p, 1);
        p += __shfl_xor_sync(0xffffffffu, p, 2);   // quad = one head
        float eh = p * rscale;
        float mn = fmaxf(m, eh);
        float corr = __expf(m - mn);
        float wgt = __expf(eh - mn);
        s = s * corr + wgt;
        acc.x = acc.x * corr + v4.x * wgt;
        acc.y = acc.y * corr + v4.y * wgt;
        acc.z = acc.z * corr + v4.z * wgt;
        acc.w = acc.w * corr + v4.w * wgt;
        m = mn;
    }
    float inv = (s > 0.f) ? 1.f / s : 0.f;

    const float4 f4 = *(const float4*)(feat + (size_t)n * FDIM + lane * 4);
    float x0 = acc.x * inv + f4.x;
    float x1 = acc.y * inv + f4.y;
    float x2 = acc.z * inv + f4.z;
    float x3 = acc.w * inv + f4.w;

    float p = x0 + x1 + x2 + x3;
#pragma unroll
    for (int o = 16; o; o >>= 1) p += __shfl_xor_sync(0xffffffffu, p, o);
    float mu = p * (1.f / 128.f);
    float d0 = x0 - mu, d1 = x1 - mu, d2 = x2 - mu, d3 = x3 - mu;
    float q = d0 * d0 + d1 * d1 + d2 * d2 + d3 * d3;
#pragma unroll
    for (int o = 16; o; o >>= 1) q += __shfl_xor_sync(0xffffffffu, q, o);
    float rs = rsqrtf(q * (1.f / 128.f) + 1e-5f);

    const float4 gv = *(const float4*)(lng + lane * 4);
    const float4 lb = *(const float4*)(lnb + lane * 4);
    float y0 = d0 * rs * gv.x + lb.x;
    float y1 = d1 * rs * gv.y + lb.y;
    float y2 = d2 * rs * gv.z + lb.z;
    float y3 = d3 * rs * gv.w + lb.w;
    size_t base = (size_t)n * FDIM + lane * 4;
    *(float4*)(g_rst + base) = make_float4(y0, y1, y2, y3);

    size_t w = base >> 1;
    ((unsigned*)g_rst16)[w] = pkh2(y0, y1);
    ((unsigned*)g_rst16)[w + 1] = pkh2(y2, y3);
}

// ---------------------------------------------------------------- launch
extern "C" void kernel_launch(void* const* d_in, const int* in_sizes, int n_in,
                              void* d_out, int out_size) {
    const float* feat = (const float*)d_in[0];
    const int* src = (const int*)d_in[1];
    const int* dst = (const int*)d_in[2];
    const float* Wq = (const float*)d_in[3];
    const float* Wk = (const float*)d_in[4];
    const float* Wv = (const float*)d_in[5];
    const float* ln1_g = (const float*)d_in[6];
    const float* ln1_b = (const float*)d_in[7];
    const float* W1 = (const float*)d_in[8];
    const float* b1 = (const float*)d_in[9];
    const float* pa = (const float*)d_in[10];
    const float* W2 = (const float*)d_in[11];
    const float* b2 = (const float*)d_in[12];
    float* out = (float*)d_out;

    const int MB128 = (NNODES + 127) / 128;  // 391

    // launch order: QKV mma at OUR index 3 == the profiled slot
    k_split_feat<<<(NNODES * FDIM / 2 + 255) / 256, 256>>>(feat);     // 0
    k_split_wall<<<(180224 + 255) / 256, 256>>>(Wq, Wk, Wv, W1, W2);  // 1
    k_zero_deg<<<SCAN_NB, 256>>>();                                   // 2
    k_gemm_qkv<<<dim3(3, MB128), 256>>>();                            // 3 <- ncu

    // CSR build
    k_hist<<<NEDGES / 256, 256>>>(dst);
    k_scan1<<<SCAN_NB, 256>>>();
    k_scan2<<<1, 256>>>();
    k_scan3<<<SCAN_NB, 256>>>();
    k_scatter<<<NEDGES / 256, 256>>>(dst);

    // attention aggregation + residual + LN1 (+ fp16 copy of rst)
    k_aggregate<<<(NNODES * 32 + 255) / 256, 256>>>(feat, src, ln1_g, ln1_b);

    // FFN (tensor cores, fp16 2-pass)
    k_ffn1<<<dim3(DFF / 128, MB128), 256>>>(b1, pa);
    k_ffn2<<<dim3(1, MB128), 256>>>(b2);
    k_ln<<<(NNODES + 7) / 8, 256>>>(ln1_g, ln1_b, out);
}

// round 13
// speedup vs baseline: 1.3887x; 1.1258x over previous
#include <cuda_runtime.h>
#include <cuda_fp16.h>
#include <math.h>

// ---------------------------------------------------------------------------
// GAT layer (round 13): single-pass plain fp16 GEMMs (C ~= A_f16 * B_f16).
// Error model (validated 2x): adds B's fp16 rounding to A's -> ~2.5e-4,
// 4x under the 1e-3 gate. Halves MMA count + B traffic vs R12.
// ---------------------------------------------------------------------------

#define NNODES 50000
#define NEDGES 640000
#define FDIM   128
#define DFF    512
#define SCAN_NB ((NNODES + 255) / 256)   // 196
#define RSTR   12                        // SMEM row stride in u32 words (48B)
#define ARRW   (128 * RSTR)              // u32 words per smem array

// fp32 scratch
__device__ __align__(16) float g_q[NNODES * FDIM];
__device__ __align__(16) float g_k[NNODES * FDIM];
__device__ __align__(16) float g_v[NNODES * FDIM];
__device__ __align__(16) float g_rst[NNODES * FDIM];
__device__ __align__(16) float g_x[NNODES * FDIM];
// fp16 activations (A operands)
__device__ __align__(16) __half g_feat16[NNODES * FDIM];
__device__ __align__(16) __half g_rst16[NNODES * FDIM];
__device__ __align__(16) __half g_hbuf16[NNODES * DFF];
// transposed fp16 weights: Wt[n][k]
__device__ __align__(16) __half g_Wqt[FDIM * FDIM];
__device__ __align__(16) __half g_Wkt[FDIM * FDIM];
__device__ __align__(16) __half g_Wvt[FDIM * FDIM];
__device__ __align__(16) __half g_W1t[DFF * FDIM];
__device__ __align__(16) __half g_W2t[FDIM * DFF];
// CSR
__device__ int g_deg[NNODES];
__device__ int g_off[NNODES + 1];
__device__ int g_eid[NEDGES];
__device__ int g_bsum[256];

// ---------------------------------------------------------------- helpers
__device__ __forceinline__ unsigned pkh2(float a, float b) {
    __half2 t = __floats2half2_rn(a, b);
    return *(unsigned*)&t;
}

#define MMA_F16(C, A0, A1, A2, A3, B0, B1)                                    \
    asm volatile(                                                             \
        "mma.sync.aligned.m16n8k16.row.col.f32.f16.f16.f32 "                  \
        "{%0,%1,%2,%3}, {%4,%5,%6,%7}, {%8,%9}, {%0,%1,%2,%3};"               \
        : "+f"((C)[0]), "+f"((C)[1]), "+f"((C)[2]), "+f"((C)[3])              \
        : "r"(A0), "r"(A1), "r"(A2), "r"(A3), "r"(B0), "r"(B1));

#define CPASYNC16(dst, src, sz)                                               \
    asm volatile("cp.async.cg.shared.global [%0], [%1], 16, %2;" ::           \
                     "r"(dst), "l"(src), "r"(sz))
#define CP_COMMIT() asm volatile("cp.async.commit_group;")
#define CP_WAIT1() asm volatile("cp.async.wait_group 1;")
#define CP_WAIT0() asm volatile("cp.async.wait_group 0;")

// one fused kernel: transpose+convert all 5 weight matrices to fp16.
__global__ void k_split_wall(const float* __restrict__ Wq,
                             const float* __restrict__ Wk,
                             const float* __restrict__ Wv,
                             const float* __restrict__ W1,
                             const float* __restrict__ W2) {
    int i = blockIdx.x * blockDim.x + threadIdx.x;
    const float* in;
    __half* oh;
    int idx, K, N;
    if (i < 16384) {
        in = Wq; oh = g_Wqt; idx = i; K = FDIM; N = FDIM;
    } else if (i < 32768) {
        in = Wk; oh = g_Wkt; idx = i - 16384; K = FDIM; N = FDIM;
    } else if (i < 49152) {
        in = Wv; oh = g_Wvt; idx = i - 32768; K = FDIM; N = FDIM;
    } else if (i < 114688) {
        in = W1; oh = g_W1t; idx = i - 49152; K = FDIM; N = DFF;
    } else if (i < 180224) {
        in = W2; oh = g_W2t; idx = i - 114688; K = DFF; N = FDIM;
    } else {
        return;
    }
    int n = idx / K, k = idx - n * K;
    oh[idx] = __float2half_rn(in[(size_t)k * N + n]);
}

// feat (fp32) -> g_feat16 fp16
__global__ void k_split_feat(const float* __restrict__ in) {
    int i = blockIdx.x * blockDim.x + threadIdx.x;   // pair index
    if (i >= NNODES * FDIM / 2) return;
    float2 v = ((const float2*)in)[i];
    ((unsigned*)g_feat16)[i] = pkh2(v.x, v.y);
}

// ---------------------------------------------------------------- CSR build
__global__ void k_zero_deg() {
    int i = blockIdx.x * blockDim.x + threadIdx.x;
    if (i < NNODES) g_deg[i] = 0;
}
__global__ void k_hist(const int* __restrict__ dst) {
    int e = blockIdx.x * blockDim.x + threadIdx.x;
    if (e < NEDGES) atomicAdd(&g_deg[dst[e]], 1);
}
__global__ void k_scan1() {
    __shared__ int s[256];
    int b = blockIdx.x, t = threadIdx.x;
    int i = b * 256 + t;
    int v = (i < NNODES) ? g_deg[i] : 0;
    s[t] = v;
    __syncthreads();
#pragma unroll
    for (int off = 1; off < 256; off <<= 1) {
        int add = (t >= off) ? s[t - off] : 0;
        __syncthreads();
        s[t] += add;
        __syncthreads();
    }
    if (i < NNODES) g_off[i + 1] = s[t];
    if (t == 255) g_bsum[b] = s[t];
}
__global__ void k_scan2() {
    __shared__ int s[256];
    int t = threadIdx.x;
    int v = (t < SCAN_NB) ? g_bsum[t] : 0;
    s[t] = v;
    __syncthreads();
#pragma unroll
    for (int off = 1; off < 256; off <<= 1) {
        int add = (t >= off) ? s[t - off] : 0;
        __syncthreads();
        s[t] += add;
        __syncthreads();
    }
    if (t < SCAN_NB) g_bsum[t] = s[t] - v;
}
// scan3 also re-zeros g_deg for the scatter pass
__global__ void k_scan3() {
    int b = blockIdx.x, t = threadIdx.x;
    int i = b * 256 + t;
    if (i < NNODES) {
        g_off[i + 1] += g_bsum[b];
        g_deg[i] = 0;
    }
    if (i == 0) g_off[0] = 0;
}
__global__ void k_scatter(const int* __restrict__ dst) {
    int e = blockIdx.x * blockDim.x + threadIdx.x;
    if (e < NEDGES) {
        int d = dst[e];
        int pos = g_off[d] + atomicAdd(&g_deg[d], 1);
        g_eid[pos] = e;
    }
}

// ------------------------------------------------- MMA GEMM core (pipelined)
// BM=128, BN=128, BK=16, 256 threads = 8 warps (2 M x 4 N), warp tile 64x32.
// A: fp16 [M,KTOT]. Bt: fp16 [N,KTOT], rows at COL0. Single mma pass.
// SMEM: 2 stages x 2 arrays (A,B) x 128 rows x RSTR u32 words.
#define GEMM_MMA_H(APTR, BT, KTOT, COL0)                                       \
    float acc[4][4][4];                                                       \
    _Pragma("unroll") for (int a_ = 0; a_ < 4; a_++)                          \
        _Pragma("unroll") for (int b_ = 0; b_ < 4; b_++)                      \
            _Pragma("unroll") for (int c_ = 0; c_ < 4; c_++)                  \
                acc[a_][b_][c_] = 0.f;                                        \
    __shared__ unsigned sm[2][2][ARRW];                                       \
    const int tid = threadIdx.x;                                              \
    const int lane = tid & 31, wid = tid >> 5;                                \
    const int wm = wid >> 2, wn = wid & 3;                                    \
    const int g = lane >> 2, tk = lane & 3;                                   \
    const int row0 = blockIdx.y * 128;                                        \
    const int lr = tid >> 1, lh = tid & 1;                                    \
    int arow = row0 + lr;                                                     \
    const unsigned okA = (arow < NNODES) ? 16u : 0u;                          \
    if (arow >= NNODES) arow = NNODES - 1;                                    \
    const int brow = (COL0) + lr;                                             \
    const __half* gsrc[2] = {(APTR) + (size_t)arow * (KTOT) + lh * 8,         \
                             (BT) + (size_t)brow * (KTOT) + lh * 8};          \
    const unsigned szs[2] = {okA, 16u};                                       \
    const unsigned smbase =                                                   \
        (unsigned)__cvta_generic_to_shared(&sm[0][0][0]) +                    \
        (unsigned)((lr * RSTR + lh * 4) * 4);                                 \
    const int NT = (KTOT) / 16;                                               \
    _Pragma("unroll") for (int a_ = 0; a_ < 2; a_++)                          \
        CPASYNC16(smbase + a_ * (ARRW * 4), gsrc[a_], szs[a_]);               \
    CP_COMMIT();                                                              \
    for (int kt = 0; kt < NT; kt++) {                                         \
        if (kt + 1 < NT) {                                                    \
            unsigned sb = smbase + ((kt + 1) & 1) * (2 * ARRW * 4);           \
            _Pragma("unroll") for (int a_ = 0; a_ < 2; a_++)                  \
                CPASYNC16(sb + a_ * (ARRW * 4), gsrc[a_] + (kt + 1) * 16,     \
                          szs[a_]);                                           \
            CP_COMMIT();                                                      \
            CP_WAIT1();                                                       \
        } else {                                                              \
            CP_WAIT0();                                                       \
        }                                                                     \
        __syncthreads();                                                      \
        const unsigned* As = sm[kt & 1][0];                                   \
        const unsigned* Bs = sm[kt & 1][1];                                   \
        unsigned ah[4][4], bh[4][2];                                          \
        _Pragma("unroll") for (int mt = 0; mt < 4; mt++) {                    \
            int br = wm * 64 + mt * 16;                                       \
            ah[mt][0] = As[(br + g) * RSTR + tk];                             \
            ah[mt][1] = As[(br + g + 8) * RSTR + tk];                         \
            ah[mt][2] = As[(br + g) * RSTR + tk + 4];                         \
            ah[mt][3] = As[(br + g + 8) * RSTR + tk + 4];                     \
        }                                                                     \
        _Pragma("unroll") for (int nt = 0; nt < 4; nt++) {                    \
            int bn = wn * 32 + nt * 8;                                        \
            bh[nt][0] = Bs[(bn + g) * RSTR + tk];                             \
            bh[nt][1] = Bs[(bn + g) * RSTR + tk + 4];                         \
        }                                                                     \
        _Pragma("unroll") for (int mt = 0; mt < 4; mt++)                      \
            _Pragma("unroll") for (int nt = 0; nt < 4; nt++)                  \
                MMA_F16(acc[mt][nt], ah[mt][0], ah[mt][1], ah[mt][2],         \
                        ah[mt][3], bh[nt][0], bh[nt][1]);                     \
        __syncthreads();                                                      \
    }

// QKV: grid (3, 391); blockIdx.x selects {q,k,v}
__global__ __launch_bounds__(256, 1) void k_gemm_qkv() {
    const int m = blockIdx.x;
    const __half* Bt = (m == 0) ? g_Wqt : (m == 1) ? g_Wkt : g_Wvt;
    float* C = (m == 0) ? g_q : (m == 1) ? g_k : g_v;
    GEMM_MMA_H(g_feat16, Bt, FDIM, 0)
#pragma unroll
    for (int mt = 0; mt < 4; mt++) {
#pragma unroll
        for (int nt = 0; nt < 4; nt++) {
            int row = row0 + wm * 64 + mt * 16 + g;
            int col = wn * 32 + nt * 8 + tk * 2;
#pragma unroll
            for (int hf = 0; hf < 2; hf++) {
                int r = row + hf * 8;
                if (r >= NNODES) continue;
                *(float2*)(C + (size_t)r * FDIM + col) =
                    make_float2(acc[mt][nt][hf * 2 + 0],
                                acc[mt][nt][hf * 2 + 1]);
            }
        }
    }
}

// FFN1: hbuf16 = PReLU(rst @ W1 + b1) ; grid (4, 391)
__global__ __launch_bounds__(256, 1) void k_ffn1(const float* __restrict__ b1,
                                                 const float* __restrict__ pa) {
    const int col0 = blockIdx.x * 128;
    GEMM_MMA_H(g_rst16, g_W1t, FDIM, col0)
#pragma unroll
    for (int mt = 0; mt < 4; mt++) {
#pragma unroll
        for (int nt = 0; nt < 4; nt++) {
            int row = row0 + wm * 64 + mt * 16 + g;
            int col = col0 + wn * 32 + nt * 8 + tk * 2;
            float bb0 = b1[col], bb1 = b1[col + 1];
            float pa0 = pa[col], pa1 = pa[col + 1];
#pragma unroll
            for (int hf = 0; hf < 2; hf++) {
                int r = row + hf * 8;
                if (r >= NNODES) continue;
                float h0 = acc[mt][nt][hf * 2 + 0] + bb0;
                float h1 = acc[mt][nt][hf * 2 + 1] + bb1;
                h0 = (h0 >= 0.f) ? h0 : pa0 * h0;
                h1 = (h1 >= 0.f) ? h1 : pa1 * h1;
                ((unsigned*)g_hbuf16)[((size_t)r * DFF + col) >> 1] =
                    pkh2(h0, h1);
            }
        }
    }
}

// FFN2: g_x = hbuf @ W2 + b2 + rst ; grid (1, 391)
__global__ __launch_bounds__(256, 1) void k_ffn2(const float* __restrict__ b2) {
    GEMM_MMA_H(g_hbuf16, g_W2t, DFF, 0)
#pragma unroll
    for (int mt = 0; mt < 4; mt++) {
#pragma unroll
        for (int nt = 0; nt < 4; nt++) {
            int row = row0 + wm * 64 + mt * 16 + g;
            int col = wn * 32 + nt * 8 + tk * 2;
            float bb0 = b2[col], bb1 = b2[col + 1];
#pragma unroll
            for (int hf = 0; hf < 2; hf++) {
                int r = row + hf * 8;
                if (r >= NNODES) continue;
                float2 rv = *(const float2*)(g_rst + (size_t)r * FDIM + col);
                *(float2*)(g_x + (size_t)r * FDIM + col) =
                    make_float2(acc[mt][nt][hf * 2 + 0] + bb0 + rv.x,
                                acc[mt][nt][hf * 2 + 1] + bb1 + rv.y);
            }
        }
    }
}

// final LN over g_x -> out ; one warp per row
__global__ __launch_bounds__(256) void k_ln(const float* __restrict__ lng,
                                            const float* __restrict__ lnb,
                                            float* __restrict__ out) {
    int n = blockIdx.x * 8 + (threadIdx.x >> 5);
    int lane = threadIdx.x & 31;
    if (n >= NNODES) return;
    float4 x = *(const float4*)(g_x + (size_t)n * FDIM + lane * 4);
    float p = x.x + x.y + x.z + x.w;
#pragma unroll
    for (int o = 16; o; o >>= 1) p += __shfl_xor_sync(0xffffffffu, p, o);
    float mu = p * (1.f / 128.f);
    float d0 = x.x - mu, d1 = x.y - mu, d2 = x.z - mu, d3 = x.w - mu;
    float q = d0 * d0 + d1 * d1 + d2 * d2 + d3 * d3;
#pragma unroll
    for (int o = 16; o; o >>= 1) q += __shfl_xor_sync(0xffffffffu, q, o);
    float rs = rsqrtf(q * (1.f / 128.f) + 1e-5f);
    const float4 gv = *(const float4*)(lng + lane * 4);
    const float4 lb = *(const float4*)(lnb + lane * 4);
    *(float4*)(out + (size_t)n * FDIM + lane * 4) =
        make_float4(d0 * rs * gv.x + lb.x, d1 * rs * gv.y + lb.y,
                    d2 * rs * gv.z + lb.z, d3 * rs * gv.w + lb.w);
}

// --------------------------------------------- attention aggregate + LN1
// one warp per dst node; online softmax per head (lane quad = head).
__global__ __launch_bounds__(256) void k_aggregate(
    const float* __restrict__ feat, const int* __restrict__ src,
    const float* __restrict__ lng, const float* __restrict__ lnb) {
    int n = (blockIdx.x * blockDim.x + threadIdx.x) >> 5;
    int lane = threadIdx.x & 31;
    if (n >= NNODES) return;

    const float4 q4 = *(const float4*)(g_q + (size_t)n * FDIM + lane * 4);
    float4 acc = make_float4(0.f, 0.f, 0.f, 0.f);
    float m = -INFINITY, s = 0.f;
    const float rscale = 0.08838834764831845f;   // 1/sqrt(128)

    int beg = g_off[n], end = g_off[n + 1];
    for (int idx = beg; idx < end; ++idx) {
        int e = g_eid[idx];
        int sn = src[e];
        const float4 k4 = *(const float4*)(g_k + (size_t)sn * FDIM + lane * 4);
        const float4 v4 = *(const float4*)(g_v + (size_t)sn * FDIM + lane * 4);
        float p = k4.x * q4.x + k4.y * q4.y + k4.z * q4.z + k4.w * q4.w;
        p += __shfl_xor_sync(0xffffffffu, p, 1);
        p += __shfl_xor_sync(0xffffffffu, p, 2);   // quad = one head
        float eh = p * rscale;
        float mn = fmaxf(m, eh);
        float corr = __expf(m - mn);
        float wgt = __expf(eh - mn);
        s = s * corr + wgt;
        acc.x = acc.x * corr + v4.x * wgt;
        acc.y = acc.y * corr + v4.y * wgt;
        acc.z = acc.z * corr + v4.z * wgt;
        acc.w = acc.w * corr + v4.w * wgt;
        m = mn;
    }
    float inv = (s > 0.f) ? 1.f / s : 0.f;

    const float4 f4 = *(const float4*)(feat + (size_t)n * FDIM + lane * 4);
    float x0 = acc.x * inv + f4.x;
    float x1 = acc.y * inv + f4.y;
    float x2 = acc.z * inv + f4.z;
    float x3 = acc.w * inv + f4.w;

    float p = x0 + x1 + x2 + x3;
#pragma unroll
    for (int o = 16; o; o >>= 1) p += __shfl_xor_sync(0xffffffffu, p, o);
    float mu = p * (1.f / 128.f);
    float d0 = x0 - mu, d1 = x1 - mu, d2 = x2 - mu, d3 = x3 - mu;
    float q = d0 * d0 + d1 * d1 + d2 * d2 + d3 * d3;
#pragma unroll
    for (int o = 16; o; o >>= 1) q += __shfl_xor_sync(0xffffffffu, q, o);
    float rs = rsqrtf(q * (1.f / 128.f) + 1e-5f);

    const float4 gv = *(const float4*)(lng + lane * 4);
    const float4 lb = *(const float4*)(lnb + lane * 4);
    float y0 = d0 * rs * gv.x + lb.x;
    float y1 = d1 * rs * gv.y + lb.y;
    float y2 = d2 * rs * gv.z + lb.z;
    float y3 = d3 * rs * gv.w + lb.w;
    size_t base = (size_t)n * FDIM + lane * 4;
    *(float4*)(g_rst + base) = make_float4(y0, y1, y2, y3);

    size_t w = base >> 1;
    ((unsigned*)g_rst16)[w] = pkh2(y0, y1);
    ((unsigned*)g_rst16)[w + 1] = pkh2(y2, y3);
}

// ---------------------------------------------------------------- launch
extern "C" void kernel_launch(void* const* d_in, const int* in_sizes, int n_in,
                              void* d_out, int out_size) {
    const float* feat = (const float*)d_in[0];
    const int* src = (const int*)d_in[1];
    const int* dst = (const int*)d_in[2];
    const float* Wq = (const float*)d_in[3];
    const float* Wk = (const float*)d_in[4];
    const float* Wv = (const float*)d_in[5];
    const float* ln1_g = (const float*)d_in[6];
    const float* ln1_b = (const float*)d_in[7];
    const float* W1 = (const float*)d_in[8];
    const float* b1 = (const float*)d_in[9];
    const float* pa = (const float*)d_in[10];
    const float* W2 = (const float*)d_in[11];
    const float* b2 = (const float*)d_in[12];
    float* out = (float*)d_out;

    const int MB128 = (NNODES + 127) / 128;  // 391

    // launch order: QKV mma at OUR index 3 == the profiled slot
    k_split_feat<<<(NNODES * FDIM / 2 + 255) / 256, 256>>>(feat);     // 0
    k_split_wall<<<(180224 + 255) / 256, 256>>>(Wq, Wk, Wv, W1, W2);  // 1
    k_zero_deg<<<SCAN_NB, 256>>>();                                   // 2
    k_gemm_qkv<<<dim3(3, MB128), 256>>>();                            // 3 <- ncu

    // CSR build
    k_hist<<<NEDGES / 256, 256>>>(dst);
    k_scan1<<<SCAN_NB, 256>>>();
    k_scan2<<<1, 256>>>();
    k_scan3<<<SCAN_NB, 256>>>();
    k_scatter<<<NEDGES / 256, 256>>>(dst);

    // attention aggregation + residual + LN1 (+ fp16 copy of rst)
    k_aggregate<<<(NNODES * 32 + 255) / 256, 256>>>(feat, src, ln1_g, ln1_b);

    // FFN (tensor cores, fp16 single-pass)
    k_ffn1<<<dim3(DFF / 128, MB128), 256>>>(b1, pa);
    k_ffn2<<<dim3(1, MB128), 256>>>(b2);
    k_ln<<<(NNODES + 7) / 8, 256>>>(ln1_g, ln1_b, out);
}